// round 1
// baseline (speedup 1.0000x reference)
#include <cuda_runtime.h>
#include <math.h>

#define Bb 8
#define Tt 1024
#define Cc 1024
#define NHEAD 16
#define HDIM 64
#define BHt (Bb*NHEAD)     // 128
#define Mm (Bb*Tt)         // 8192
#define N1 (3*Cc)          // 3072

// Scratch (device globals; allocation in kernel_launch is forbidden)
__device__ float g_Q[(size_t)BHt*Tt*HDIM];   // [bh][t][d]
__device__ float g_K[(size_t)BHt*Tt*HDIM];
__device__ float g_V[(size_t)BHt*Tt*HDIM];
__device__ float g_Y[(size_t)Mm*Cc];         // [b][t][c] attention output

// ---------------------------------------------------------------------------
// NT SGEMM: C[m,n] = sum_k A[m,k] * Bw[n,k] + bias[n]
// 128x128 tile, BK=8, 256 threads, 8x8 micro-tile per thread.
// MODE 0: scatter into g_Q/g_K/g_V head-major layout (QKV projection)
// MODE 1: A is g_Y, plain row-major store to Cout (output projection)
// ---------------------------------------------------------------------------
template<int MODE>
__global__ __launch_bounds__(256)
void sgemm_nt_kernel(const float* __restrict__ A,
                     const float* __restrict__ Bw,
                     const float* __restrict__ bias,
                     float* __restrict__ Cout,
                     int M, int N, int K)
{
    __shared__ float As[8][128];
    __shared__ float Bs[8][128];

    const float* Ap = (MODE == 1) ? (const float*)g_Y : A;

    int tid  = threadIdx.x;
    int m0   = blockIdx.y * 128;
    int n0   = blockIdx.x * 128;
    int tx   = tid & 15;
    int ty   = tid >> 4;
    int lrow = tid >> 1;          // 0..127
    int lk4  = (tid & 1) * 4;     // 0 or 4

    float acc[8][8];
    #pragma unroll
    for (int i = 0; i < 8; i++)
        #pragma unroll
        for (int j = 0; j < 8; j++)
            acc[i][j] = 0.0f;

    const float* Aptr = Ap + (size_t)(m0 + lrow) * K + lk4;
    const float* Bptr = Bw + (size_t)(n0 + lrow) * K + lk4;

    for (int kt = 0; kt < K; kt += 8) {
        float4 av = *(const float4*)(Aptr + kt);
        float4 bv = *(const float4*)(Bptr + kt);
        As[lk4+0][lrow] = av.x; As[lk4+1][lrow] = av.y;
        As[lk4+2][lrow] = av.z; As[lk4+3][lrow] = av.w;
        Bs[lk4+0][lrow] = bv.x; Bs[lk4+1][lrow] = bv.y;
        Bs[lk4+2][lrow] = bv.z; Bs[lk4+3][lrow] = bv.w;
        __syncthreads();

        #pragma unroll
        for (int k = 0; k < 8; k++) {
            float a[8], b[8];
            *(float4*)(a)     = *(const float4*)&As[k][ty*4];
            *(float4*)(a + 4) = *(const float4*)&As[k][64 + ty*4];
            *(float4*)(b)     = *(const float4*)&Bs[k][tx*4];
            *(float4*)(b + 4) = *(const float4*)&Bs[k][64 + tx*4];
            #pragma unroll
            for (int i = 0; i < 8; i++)
                #pragma unroll
                for (int j = 0; j < 8; j++)
                    acc[i][j] += a[i] * b[j];
        }
        __syncthreads();
    }

    #pragma unroll
    for (int i = 0; i < 8; i++) {
        int m = m0 + ty*4 + (i & 3) + ((i >> 2) << 6);
        #pragma unroll
        for (int j = 0; j < 8; j++) {
            int n = n0 + tx*4 + (j & 3) + ((j >> 2) << 6);
            float v = acc[i][j] + bias[n];
            if (MODE == 0) {
                int which = n >> 10;           // 0=q 1=k 2=v (tile-constant)
                int c = n & 1023;
                int h = c >> 6, d = c & 63;
                int b = m >> 10, t = m & 1023;
                float* buf = (which == 0) ? g_Q : ((which == 1) ? g_K : g_V);
                buf[(size_t)((b*NHEAD + h)*Tt + t)*HDIM + d] = v;
            } else {
                Cout[(size_t)m * N + n] = v;
            }
        }
    }
}

// ---------------------------------------------------------------------------
// RoPE in place on g_Q and g_K. One thread per (bh, t, pair).
// ---------------------------------------------------------------------------
__global__ __launch_bounds__(256)
void rope_kernel()
{
    int idx = blockIdx.x * blockDim.x + threadIdx.x; // BHt*Tt*32 threads
    int i  = idx & 31;           // pair index 0..31
    int t  = (idx >> 5) & 1023;
    int bh = idx >> 15;

    // inv_freq = 10000^(-i/32), accurate path
    float inv = expf(-(float)i * (logf(10000.0f) / 32.0f));
    float ang = (float)t * inv;
    float sv, cv;
    sincosf(ang, &sv, &cv);

    size_t base = (size_t)(bh * Tt + t) * HDIM + 2*i;
    float x1 = g_Q[base], x2 = g_Q[base + 1];
    g_Q[base]     = x1*cv - x2*sv;
    g_Q[base + 1] = x2*cv + x1*sv;
    x1 = g_K[base]; x2 = g_K[base + 1];
    g_K[base]     = x1*cv - x2*sv;
    g_K[base + 1] = x2*cv + x1*sv;
}

// ---------------------------------------------------------------------------
// Flash attention fp32, causal. One block = (bh, 64-row q-tile).
// 256 threads. Thread (g=tid/16, q=tid%16) owns S rows g*4..g*4+3 and
// cols {q, q+16, q+32, q+48}; same mapping for output d-columns.
// Shared: Qs[64][64], Vs[64][64], Ps[64][64], Ks[64][65] (padded).
// ---------------------------------------------------------------------------
__global__ __launch_bounds__(256)
void flash_attn_kernel()
{
    extern __shared__ float sm[];
    float* Qs = sm;               // 4096
    float* Vs = Qs + 4096;        // 4096
    float* Ps = Vs + 4096;        // 4096
    float* Ks = Ps + 4096;        // 64*65 = 4160

    int tid = threadIdx.x;
    int qt  = blockIdx.x;         // 0..15
    int bh  = blockIdx.y;         // 0..127

    const float* Qg = g_Q + (size_t)(bh * Tt + qt * 64) * HDIM;
    const float* Kg = g_K + (size_t)bh * Tt * HDIM;
    const float* Vg = g_V + (size_t)bh * Tt * HDIM;

    // load Q tile (pre-scaled by 1/sqrt(64))
    #pragma unroll
    for (int ii = 0; ii < 16; ii++) {
        int e = tid + 256 * ii;
        Qs[e] = Qg[e] * 0.125f;
    }

    int g  = tid >> 4;
    int q  = tid & 15;
    int r0 = g * 4;

    float mrow[4], lsum[4], acc[4][4];
    #pragma unroll
    for (int i = 0; i < 4; i++) {
        mrow[i] = -1e30f; lsum[i] = 0.0f;
        #pragma unroll
        for (int jj = 0; jj < 4; jj++) acc[i][jj] = 0.0f;
    }

    for (int kt = 0; kt <= qt; kt++) {
        const float* Kt = Kg + (size_t)kt * 64 * HDIM;
        const float* Vt = Vg + (size_t)kt * 64 * HDIM;
        #pragma unroll
        for (int ii = 0; ii < 16; ii++) {
            int e = tid + 256 * ii;
            int r = e >> 6, c = e & 63;
            Ks[r * 65 + c] = Kt[e];
            Vs[e] = Vt[e];
        }
        __syncthreads();

        // S = Q K^T (4x4 per thread)
        float s[4][4];
        #pragma unroll
        for (int i = 0; i < 4; i++)
            #pragma unroll
            for (int jj = 0; jj < 4; jj++) s[i][jj] = 0.0f;

        #pragma unroll 16
        for (int k = 0; k < 64; k++) {
            float a0 = Qs[(r0+0)*64 + k];
            float a1 = Qs[(r0+1)*64 + k];
            float a2 = Qs[(r0+2)*64 + k];
            float a3 = Qs[(r0+3)*64 + k];
            float b0 = Ks[(q     )*65 + k];
            float b1 = Ks[(q + 16)*65 + k];
            float b2 = Ks[(q + 32)*65 + k];
            float b3 = Ks[(q + 48)*65 + k];
            s[0][0] += a0*b0; s[0][1] += a0*b1; s[0][2] += a0*b2; s[0][3] += a0*b3;
            s[1][0] += a1*b0; s[1][1] += a1*b1; s[1][2] += a1*b2; s[1][3] += a1*b3;
            s[2][0] += a2*b0; s[2][1] += a2*b1; s[2][2] += a2*b2; s[2][3] += a2*b3;
            s[3][0] += a3*b0; s[3][1] += a3*b1; s[3][2] += a3*b2; s[3][3] += a3*b3;
        }

        // causal mask on diagonal tile
        if (kt == qt) {
            #pragma unroll
            for (int i = 0; i < 4; i++)
                #pragma unroll
                for (int jj = 0; jj < 4; jj++)
                    if (q + 16*jj > r0 + i) s[i][jj] = -1e30f;
        }

        // online softmax per row (row stats across the 16-lane group)
        #pragma unroll
        for (int i = 0; i < 4; i++) {
            float tm = fmaxf(fmaxf(s[i][0], s[i][1]), fmaxf(s[i][2], s[i][3]));
            tm = fmaxf(tm, __shfl_xor_sync(0xffffffffu, tm, 1));
            tm = fmaxf(tm, __shfl_xor_sync(0xffffffffu, tm, 2));
            tm = fmaxf(tm, __shfl_xor_sync(0xffffffffu, tm, 4));
            tm = fmaxf(tm, __shfl_xor_sync(0xffffffffu, tm, 8));
            float mn    = fmaxf(mrow[i], tm);
            float alpha = __expf(mrow[i] - mn);
            mrow[i] = mn;
            float ts = 0.0f;
            #pragma unroll
            for (int jj = 0; jj < 4; jj++) {
                float p = __expf(s[i][jj] - mn);
                s[i][jj] = p;
                ts += p;
            }
            ts += __shfl_xor_sync(0xffffffffu, ts, 1);
            ts += __shfl_xor_sync(0xffffffffu, ts, 2);
            ts += __shfl_xor_sync(0xffffffffu, ts, 4);
            ts += __shfl_xor_sync(0xffffffffu, ts, 8);
            lsum[i] = lsum[i] * alpha + ts;
            #pragma unroll
            for (int jj = 0; jj < 4; jj++) acc[i][jj] *= alpha;
            #pragma unroll
            for (int jj = 0; jj < 4; jj++)
                Ps[(r0 + i) * 64 + q + 16*jj] = s[i][jj];
        }
        __syncthreads();

        // acc += P V
        #pragma unroll 16
        for (int j = 0; j < 64; j++) {
            float p0 = Ps[(r0+0)*64 + j];
            float p1 = Ps[(r0+1)*64 + j];
            float p2 = Ps[(r0+2)*64 + j];
            float p3 = Ps[(r0+3)*64 + j];
            float v0 = Vs[j*64 + q];
            float v1 = Vs[j*64 + q + 16];
            float v2 = Vs[j*64 + q + 32];
            float v3 = Vs[j*64 + q + 48];
            acc[0][0] += p0*v0; acc[0][1] += p0*v1; acc[0][2] += p0*v2; acc[0][3] += p0*v3;
            acc[1][0] += p1*v0; acc[1][1] += p1*v1; acc[1][2] += p1*v2; acc[1][3] += p1*v3;
            acc[2][0] += p2*v0; acc[2][1] += p2*v1; acc[2][2] += p2*v2; acc[2][3] += p2*v3;
            acc[3][0] += p3*v0; acc[3][1] += p3*v1; acc[3][2] += p3*v2; acc[3][3] += p3*v3;
        }
        __syncthreads();
    }

    // write y in [B, T, C] layout for GEMM2
    int b = bh >> 4, h = bh & 15;
    #pragma unroll
    for (int i = 0; i < 4; i++) {
        float inv = 1.0f / lsum[i];
        int trow = qt * 64 + r0 + i;
        float* yp = g_Y + (size_t)(b * Tt + trow) * Cc + h * HDIM;
        #pragma unroll
        for (int jj = 0; jj < 4; jj++)
            yp[q + 16*jj] = acc[i][jj] * inv;
    }
}

// ---------------------------------------------------------------------------
extern "C" void kernel_launch(void* const* d_in, const int* in_sizes, int n_in,
                              void* d_out, int out_size)
{
    (void)in_sizes; (void)n_in; (void)out_size;
    const float* x   = (const float*)d_in[0];
    const float* ipw = (const float*)d_in[1];
    const float* ipb = (const float*)d_in[2];
    const float* opw = (const float*)d_in[3];
    const float* opb = (const float*)d_in[4];
    float* out = (float*)d_out;

    // 1) QKV projection + bias + head-major scatter
    {
        dim3 grid(N1 / 128, Mm / 128);   // (24, 64)
        sgemm_nt_kernel<0><<<grid, 256>>>(x, ipw, ipb, nullptr, Mm, N1, Cc);
    }

    // 2) RoPE on Q, K
    {
        int total = BHt * Tt * 32;
        rope_kernel<<<total / 256, 256>>>();
    }

    // 3) causal flash attention -> g_Y in [B,T,C]
    {
        size_t smem = (size_t)(4096 * 3 + 64 * 65) * sizeof(float);  // 65792 B
        cudaFuncSetAttribute(flash_attn_kernel,
                             cudaFuncAttributeMaxDynamicSharedMemorySize,
                             (int)smem);
        dim3 grid(Tt / 64, BHt);         // (16, 128)
        flash_attn_kernel<<<grid, 256, smem>>>();
    }

    // 4) output projection + bias
    {
        dim3 grid(Cc / 128, Mm / 128);   // (8, 64)
        sgemm_nt_kernel<1><<<grid, 256>>>(nullptr, opw, opb, out, Mm, Cc, Cc);
    }
}

// round 3
// speedup vs baseline: 1.9927x; 1.9927x over previous
#include <cuda_runtime.h>
#include <cuda_bf16.h>
#include <math.h>
#include <stdint.h>

#define Bb 8
#define Tt 1024
#define Cc 1024
#define NHEAD 16
#define HDIM 64
#define BHt (Bb*NHEAD)     // 128
#define Mm (Bb*Tt)         // 8192
#define N1 (3*Cc)          // 3072
#define KT 32              // 1024/32 k-tiles

// ------------------------- device scratch (no allocs allowed) --------------
__device__ __nv_bfloat16 g_xhi[(size_t)Mm*Cc],  g_xlo[(size_t)Mm*Cc];
__device__ __nv_bfloat16 g_w1hi[(size_t)N1*Cc], g_w1lo[(size_t)N1*Cc];
__device__ __nv_bfloat16 g_w2hi[(size_t)Cc*Cc], g_w2lo[(size_t)Cc*Cc];
__device__ __nv_bfloat16 g_yhi[(size_t)Mm*Cc],  g_ylo[(size_t)Mm*Cc];
__device__ float g_Q [(size_t)BHt*Tt*HDIM];   // [bh][t][d]
__device__ float g_K [(size_t)BHt*Tt*HDIM];   // [bh][t][d]
__device__ float g_Vt[(size_t)BHt*HDIM*Tt];   // [bh][d][t]  (transposed!)

// ------------------------------ PTX helpers --------------------------------
__device__ __forceinline__ uint32_t smem_u32(const void* p) {
    uint32_t a;
    asm("{ .reg .u64 t; cvta.to.shared.u64 t, %1; cvt.u32.u64 %0, t; }"
        : "=r"(a) : "l"(p));
    return a;
}

#define CP16(dst, src) \
    asm volatile("cp.async.cg.shared.global [%0], [%1], 16;" \
                 :: "r"(dst), "l"(src) : "memory")
#define CP_COMMIT() asm volatile("cp.async.commit_group;" ::: "memory")
#define CP_WAIT1()  asm volatile("cp.async.wait_group 1;" ::: "memory")
#define CP_WAIT0()  asm volatile("cp.async.wait_group 0;" ::: "memory")

#define LDSM4(r0, r1, r2, r3, a) \
    asm volatile("ldmatrix.sync.aligned.m8n8.x4.shared.b16 {%0,%1,%2,%3}, [%4];" \
                 : "=r"(r0), "=r"(r1), "=r"(r2), "=r"(r3) : "r"(a))

__device__ __forceinline__ void mma16816(float c[4], const uint32_t a[4],
                                         uint32_t b0, uint32_t b1) {
    asm volatile("mma.sync.aligned.m16n8k16.row.col.f32.bf16.bf16.f32 "
                 "{%0,%1,%2,%3}, {%4,%5,%6,%7}, {%8,%9}, {%0,%1,%2,%3};"
                 : "+f"(c[0]), "+f"(c[1]), "+f"(c[2]), "+f"(c[3])
                 : "r"(a[0]), "r"(a[1]), "r"(a[2]), "r"(a[3]),
                   "r"(b0), "r"(b1));
}

// ---------------------------------------------------------------------------
// fp32 -> bf16 hi/lo split conversion (one pass per source array)
// ---------------------------------------------------------------------------
template<int W>
__global__ __launch_bounds__(256)
void cvt_kernel(const float* __restrict__ src, int n4)
{
    int i = blockIdx.x * blockDim.x + threadIdx.x;
    if (i >= n4) return;
    __nv_bfloat16* hi = (W == 0) ? g_xhi : (W == 1) ? g_w1hi : g_w2hi;
    __nv_bfloat16* lo = (W == 0) ? g_xlo : (W == 1) ? g_w1lo : g_w2lo;
    float4 v = ((const float4*)src)[i];
    __nv_bfloat162 h01 = __floats2bfloat162_rn(v.x, v.y);
    __nv_bfloat162 h23 = __floats2bfloat162_rn(v.z, v.w);
    float2 f01 = __bfloat1622float2(h01);
    float2 f23 = __bfloat1622float2(h23);
    __nv_bfloat162 l01 = __floats2bfloat162_rn(v.x - f01.x, v.y - f01.y);
    __nv_bfloat162 l23 = __floats2bfloat162_rn(v.z - f23.x, v.w - f23.y);
    ((__nv_bfloat162*)hi)[i*2]     = h01;
    ((__nv_bfloat162*)hi)[i*2 + 1] = h23;
    ((__nv_bfloat162*)lo)[i*2]     = l01;
    ((__nv_bfloat162*)lo)[i*2 + 1] = l23;
}

// ---------------------------------------------------------------------------
// bf16x3 NT GEMM via mma.sync: C[m,n] = sum_k A[m,k]*B[n,k] + bias[n]
// 128x128 tile, BK=32, 256 threads, 8 warps (2x4 -> 64x32 warp tiles).
// Double-buffered cp.async. Smem tiles pitch 80B (conflict-free ldmatrix).
// MODE 0: QKV (A=x, B=w1) scatter to g_Q/g_K/g_Vt.  MODE 1: A=y, B=w2 -> Cout.
// ---------------------------------------------------------------------------
#define T_AHI 0
#define T_ALO 10240
#define T_BHI 20480
#define T_BLO 30720
#define STAGE_BYTES 40960
#define GEMM_SMEM (2*STAGE_BYTES)

__device__ __forceinline__ void gemm_prefetch(uint32_t sdst,
    const __nv_bfloat16* a_hi, const __nv_bfloat16* a_lo,
    const __nv_bfloat16* b_hi, const __nv_bfloat16* b_lo)
{
    CP16(sdst + T_AHI,      a_hi);
    CP16(sdst + T_AHI + 16, a_hi + 8);
    CP16(sdst + T_ALO,      a_lo);
    CP16(sdst + T_ALO + 16, a_lo + 8);
    CP16(sdst + T_BHI,      b_hi);
    CP16(sdst + T_BHI + 16, b_hi + 8);
    CP16(sdst + T_BLO,      b_lo);
    CP16(sdst + T_BLO + 16, b_lo + 8);
}

__device__ __forceinline__ void scatter_qkv(int m, int n, float2 v)
{
    int which = n >> 10, c = n & 1023;
    int h = c >> 6, d = c & 63;
    int b = m >> 10, t = m & 1023, bh = b * NHEAD + h;
    if (which == 0) {
        *(float2*)&g_Q[((size_t)bh * Tt + t) * HDIM + d] = v;
    } else if (which == 1) {
        *(float2*)&g_K[((size_t)bh * Tt + t) * HDIM + d] = v;
    } else {
        g_Vt[((size_t)bh * HDIM + d    ) * Tt + t] = v.x;
        g_Vt[((size_t)bh * HDIM + d + 1) * Tt + t] = v.y;
    }
}

template<int MODE>
__global__ __launch_bounds__(256)
void gemm_bf16x3(const float* __restrict__ bias, float* __restrict__ Cout)
{
    extern __shared__ char smem[];
    const uint32_t sb = smem_u32(smem);
    const int tid  = threadIdx.x;
    const int lane = tid & 31, wid = tid >> 5;
    const int wm = wid >> 2, wn = wid & 3;         // 2 x 4 warp grid
    const int m0 = blockIdx.y * 128, n0 = blockIdx.x * 128;

    const __nv_bfloat16* Ahi = (MODE == 0) ? g_xhi  : g_yhi;
    const __nv_bfloat16* Alo = (MODE == 0) ? g_xlo  : g_ylo;
    const __nv_bfloat16* Bhi = (MODE == 0) ? g_w1hi : g_w2hi;
    const __nv_bfloat16* Blo = (MODE == 0) ? g_w1lo : g_w2lo;

    // cp.async assignment: thread -> row (tid>>1), 16-elem half (tid&1)
    const int lr = tid >> 1;
    const int lh = tid & 1;
    const size_t gA = (size_t)(m0 + lr) * Cc + lh * 16;
    const size_t gB = (size_t)(n0 + lr) * Cc + lh * 16;
    const uint32_t sOff = (uint32_t)lr * 80 + lh * 32;

    // ldmatrix lane geometry
    const int jq = lane >> 3, rr = lane & 7;
    const int aRow  = wm * 64 + (jq & 1) * 8 + rr;   // + mf*16
    const int aColB = (jq >> 1) * 16;                // + kk*32 (bytes)
    const int bRow  = wn * 32 + (jq >> 1) * 8 + rr;  // + pf*16
    const int bColB = (jq & 1) * 16;

    float acc[4][4][4];
    #pragma unroll
    for (int i = 0; i < 4; i++)
        #pragma unroll
        for (int j = 0; j < 4; j++)
            #pragma unroll
            for (int e = 0; e < 4; e++) acc[i][j][e] = 0.0f;

    gemm_prefetch(sb + sOff, Ahi + gA, Alo + gA, Bhi + gB, Blo + gB);
    CP_COMMIT();

    for (int kt = 0; kt < KT; kt++) {
        const int cur = kt & 1;
        if (kt + 1 < KT) {
            const size_t ko = (size_t)(kt + 1) * 32;
            gemm_prefetch(sb + ((kt + 1) & 1) * STAGE_BYTES + sOff,
                          Ahi + gA + ko, Alo + gA + ko,
                          Bhi + gB + ko, Blo + gB + ko);
            CP_COMMIT();
            CP_WAIT1();
        } else {
            CP_WAIT0();
        }
        __syncthreads();

        const uint32_t base = sb + cur * STAGE_BYTES;
        #pragma unroll
        for (int kk = 0; kk < 2; kk++) {          // two K=16 steps per BK=32
            const uint32_t kB = kk * 32;
            uint32_t ah[4][4], al[4][4];
            #pragma unroll
            for (int mf = 0; mf < 4; mf++) {
                uint32_t addr = base + (uint32_t)(aRow + mf * 16) * 80 + aColB + kB;
                LDSM4(ah[mf][0], ah[mf][1], ah[mf][2], ah[mf][3], addr + T_AHI);
                LDSM4(al[mf][0], al[mf][1], al[mf][2], al[mf][3], addr + T_ALO);
            }
            uint32_t bh[2][4], bl[2][4];
            #pragma unroll
            for (int pf = 0; pf < 2; pf++) {
                uint32_t addr = base + (uint32_t)(bRow + pf * 16) * 80 + bColB + kB;
                LDSM4(bh[pf][0], bh[pf][1], bh[pf][2], bh[pf][3], addr + T_BHI);
                LDSM4(bl[pf][0], bl[pf][1], bl[pf][2], bl[pf][3], addr + T_BLO);
            }
            #pragma unroll
            for (int mf = 0; mf < 4; mf++) {
                #pragma unroll
                for (int nt = 0; nt < 4; nt++) {
                    const int pf = nt >> 1, ix = (nt & 1) * 2;
                    mma16816(acc[mf][nt], ah[mf], bh[pf][ix], bh[pf][ix + 1]);
                    mma16816(acc[mf][nt], ah[mf], bl[pf][ix], bl[pf][ix + 1]);
                    mma16816(acc[mf][nt], al[mf], bh[pf][ix], bh[pf][ix + 1]);
                }
            }
        }
        __syncthreads();
    }

    // epilogue
    const int gid = lane >> 2, tg = lane & 3;
    #pragma unroll
    for (int mf = 0; mf < 4; mf++) {
        #pragma unroll
        for (int nt = 0; nt < 4; nt++) {
            const int n = n0 + wn * 32 + nt * 8 + tg * 2;
            const float2 bv = *(const float2*)&bias[n];
            const int mA = m0 + wm * 64 + mf * 16 + gid;
            float2 v01 = make_float2(acc[mf][nt][0] + bv.x, acc[mf][nt][1] + bv.y);
            float2 v23 = make_float2(acc[mf][nt][2] + bv.x, acc[mf][nt][3] + bv.y);
            if (MODE == 0) {
                scatter_qkv(mA,     n, v01);
                scatter_qkv(mA + 8, n, v23);
            } else {
                *(float2*)&Cout[(size_t)mA * Cc + n]       = v01;
                *(float2*)&Cout[(size_t)(mA + 8) * Cc + n] = v23;
            }
        }
    }
}

// ---------------------------------------------------------------------------
// RoPE in place on g_Q and g_K. One thread per (bh, t, pair).
// ---------------------------------------------------------------------------
__global__ __launch_bounds__(256)
void rope_kernel()
{
    int idx = blockIdx.x * blockDim.x + threadIdx.x;
    int i  = idx & 31;
    int t  = (idx >> 5) & 1023;
    int bh = idx >> 15;

    float inv = expf(-(float)i * (logf(10000.0f) / 32.0f));
    float ang = (float)t * inv;
    float sv, cv;
    sincosf(ang, &sv, &cv);

    size_t base = (size_t)(bh * Tt + t) * HDIM + 2 * i;
    float x1 = g_Q[base], x2 = g_Q[base + 1];
    g_Q[base]     = x1 * cv - x2 * sv;
    g_Q[base + 1] = x2 * cv + x1 * sv;
    x1 = g_K[base]; x2 = g_K[base + 1];
    g_K[base]     = x1 * cv - x2 * sv;
    g_K[base + 1] = x2 * cv + x1 * sv;
}

// ---------------------------------------------------------------------------
// Flash attention fp32, causal, vectorized. Block = (q-tile, bh), 256 thr.
// V read from g_Vt [bh][d][t]; output written as bf16 hi/lo for GEMM2.
// Smem: Qs[64][64], Ps[64][64], Ks[64][68], Vt[64][68].
// ---------------------------------------------------------------------------
#define FL_SMEM ((4096*2 + 64*68*2) * 4)

__global__ __launch_bounds__(256)
void flash_attn_kernel()
{
    extern __shared__ float sm[];
    float* Qs = sm;                 // 64*64
    float* Ps = Qs + 4096;          // 64*64
    float* Ks = Ps + 4096;          // 64*68 (pad)
    float* Vt = Ks + 64 * 68;       // 64*68 (pad), Vt[d][j]

    const int tid = threadIdx.x;
    const int qt  = blockIdx.x;     // 0..15
    const int bh  = blockIdx.y;     // 0..127

    const float* Qg = g_Q  + ((size_t)bh * Tt + qt * 64) * HDIM;
    const float* Kg = g_K  + (size_t)bh * Tt * HDIM;
    const float* Vg = g_Vt + (size_t)bh * HDIM * Tt;

    #pragma unroll
    for (int ii = 0; ii < 4; ii++) {
        int i4 = tid + 256 * ii;            // 0..1023 float4s
        int r = i4 >> 4, c = (i4 & 15) * 4;
        float4 v = *(const float4*)&Qg[r * 64 + c];
        v.x *= 0.125f; v.y *= 0.125f; v.z *= 0.125f; v.w *= 0.125f;
        *(float4*)&Qs[r * 64 + c] = v;
    }

    const int g  = tid >> 4;
    const int q  = tid & 15;
    const int r0 = g * 4;

    float mrow[4], lsum[4], acc[4][4];
    #pragma unroll
    for (int i = 0; i < 4; i++) {
        mrow[i] = -1e30f; lsum[i] = 0.0f;
        #pragma unroll
        for (int jj = 0; jj < 4; jj++) acc[i][jj] = 0.0f;
    }

    for (int kt = 0; kt <= qt; kt++) {
        #pragma unroll
        for (int ii = 0; ii < 4; ii++) {
            int i4 = tid + 256 * ii;
            int r = i4 >> 4, c = (i4 & 15) * 4;
            *(float4*)&Ks[r * 68 + c] = *(const float4*)&Kg[(kt * 64 + r) * 64 + c];
            *(float4*)&Vt[r * 68 + c] = *(const float4*)&Vg[(size_t)r * Tt + kt * 64 + c];
        }
        __syncthreads();

        float s[4][4];
        #pragma unroll
        for (int i = 0; i < 4; i++)
            #pragma unroll
            for (int jj = 0; jj < 4; jj++) s[i][jj] = 0.0f;

        #pragma unroll 4
        for (int k = 0; k < 64; k += 4) {
            float4 a0 = *(const float4*)&Qs[(r0 + 0) * 64 + k];
            float4 a1 = *(const float4*)&Qs[(r0 + 1) * 64 + k];
            float4 a2 = *(const float4*)&Qs[(r0 + 2) * 64 + k];
            float4 a3 = *(const float4*)&Qs[(r0 + 3) * 64 + k];
            float4 b0 = *(const float4*)&Ks[(q     ) * 68 + k];
            float4 b1 = *(const float4*)&Ks[(q + 16) * 68 + k];
            float4 b2 = *(const float4*)&Ks[(q + 32) * 68 + k];
            float4 b3 = *(const float4*)&Ks[(q + 48) * 68 + k];
            #define QK(i, a) \
                s[i][0] += a.x*b0.x + a.y*b0.y + a.z*b0.z + a.w*b0.w; \
                s[i][1] += a.x*b1.x + a.y*b1.y + a.z*b1.z + a.w*b1.w; \
                s[i][2] += a.x*b2.x + a.y*b2.y + a.z*b2.z + a.w*b2.w; \
                s[i][3] += a.x*b3.x + a.y*b3.y + a.z*b3.z + a.w*b3.w;
            QK(0, a0) QK(1, a1) QK(2, a2) QK(3, a3)
            #undef QK
        }

        if (kt == qt) {
            #pragma unroll
            for (int i = 0; i < 4; i++)
                #pragma unroll
                for (int jj = 0; jj < 4; jj++)
                    if (q + 16 * jj > r0 + i) s[i][jj] = -1e30f;
        }

        #pragma unroll
        for (int i = 0; i < 4; i++) {
            float tm = fmaxf(fmaxf(s[i][0], s[i][1]), fmaxf(s[i][2], s[i][3]));
            tm = fmaxf(tm, __shfl_xor_sync(0xffffffffu, tm, 1));
            tm = fmaxf(tm, __shfl_xor_sync(0xffffffffu, tm, 2));
            tm = fmaxf(tm, __shfl_xor_sync(0xffffffffu, tm, 4));
            tm = fmaxf(tm, __shfl_xor_sync(0xffffffffu, tm, 8));
            float mn    = fmaxf(mrow[i], tm);
            float alpha = __expf(mrow[i] - mn);
            mrow[i] = mn;
            float ts = 0.0f;
            #pragma unroll
            for (int jj = 0; jj < 4; jj++) {
                float p = __expf(s[i][jj] - mn);
                s[i][jj] = p;
                ts += p;
            }
            ts += __shfl_xor_sync(0xffffffffu, ts, 1);
            ts += __shfl_xor_sync(0xffffffffu, ts, 2);
            ts += __shfl_xor_sync(0xffffffffu, ts, 4);
            ts += __shfl_xor_sync(0xffffffffu, ts, 8);
            lsum[i] = lsum[i] * alpha + ts;
            #pragma unroll
            for (int jj = 0; jj < 4; jj++) acc[i][jj] *= alpha;
            #pragma unroll
            for (int jj = 0; jj < 4; jj++)
                Ps[(r0 + i) * 64 + q + 16 * jj] = s[i][jj];
        }
        __syncthreads();

        #pragma unroll 4
        for (int j = 0; j < 64; j += 4) {
            float4 p0 = *(const float4*)&Ps[(r0 + 0) * 64 + j];
            float4 p1 = *(const float4*)&Ps[(r0 + 1) * 64 + j];
            float4 p2 = *(const float4*)&Ps[(r0 + 2) * 64 + j];
            float4 p3 = *(const float4*)&Ps[(r0 + 3) * 64 + j];
            float4 v0 = *(const float4*)&Vt[(q     ) * 68 + j];
            float4 v1 = *(const float4*)&Vt[(q + 16) * 68 + j];
            float4 v2 = *(const float4*)&Vt[(q + 32) * 68 + j];
            float4 v3 = *(const float4*)&Vt[(q + 48) * 68 + j];
            #define PV(i, p) \
                acc[i][0] += p.x*v0.x + p.y*v0.y + p.z*v0.z + p.w*v0.w; \
                acc[i][1] += p.x*v1.x + p.y*v1.y + p.z*v1.z + p.w*v1.w; \
                acc[i][2] += p.x*v2.x + p.y*v2.y + p.z*v2.z + p.w*v2.w; \
                acc[i][3] += p.x*v3.x + p.y*v3.y + p.z*v3.z + p.w*v3.w;
            PV(0, p0) PV(1, p1) PV(2, p2) PV(3, p3)
            #undef PV
        }
        __syncthreads();
    }

    // write y as bf16 hi/lo in [B,T,C] layout (input to GEMM2)
    const int b = bh >> 4, h = bh & 15;
    #pragma unroll
    for (int i = 0; i < 4; i++) {
        const float inv = 1.0f / lsum[i];
        const int trow = qt * 64 + r0 + i;
        const size_t yb = ((size_t)(b * Tt + trow)) * Cc + h * HDIM;
        #pragma unroll
        for (int jj = 0; jj < 4; jj++) {
            float val = acc[i][jj] * inv;
            __nv_bfloat16 hv = __float2bfloat16(val);
            g_yhi[yb + q + 16 * jj] = hv;
            g_ylo[yb + q + 16 * jj] =
                __float2bfloat16(val - __bfloat162float(hv));
        }
    }
}

// ---------------------------------------------------------------------------
extern "C" void kernel_launch(void* const* d_in, const int* in_sizes, int n_in,
                              void* d_out, int out_size)
{
    (void)in_sizes; (void)n_in; (void)out_size;
    const float* x   = (const float*)d_in[0];
    const float* ipw = (const float*)d_in[1];
    const float* ipb = (const float*)d_in[2];
    const float* opw = (const float*)d_in[3];
    const float* opb = (const float*)d_in[4];
    float* out = (float*)d_out;

    cudaFuncSetAttribute(gemm_bf16x3<0>,
                         cudaFuncAttributeMaxDynamicSharedMemorySize, GEMM_SMEM);
    cudaFuncSetAttribute(gemm_bf16x3<1>,
                         cudaFuncAttributeMaxDynamicSharedMemorySize, GEMM_SMEM);
    cudaFuncSetAttribute(flash_attn_kernel,
                         cudaFuncAttributeMaxDynamicSharedMemorySize, FL_SMEM);

    // 0) hi/lo bf16 conversions of x and weights
    cvt_kernel<0><<<(Mm*Cc/4 + 255)/256, 256>>>(x,   Mm*Cc/4);
    cvt_kernel<1><<<(N1*Cc/4 + 255)/256, 256>>>(ipw, N1*Cc/4);
    cvt_kernel<2><<<(Cc*Cc/4 + 255)/256, 256>>>(opw, Cc*Cc/4);

    // 1) QKV projection + bias + head-major scatter (V transposed)
    {
        dim3 grid(N1 / 128, Mm / 128);   // (24, 64)
        gemm_bf16x3<0><<<grid, 256, GEMM_SMEM>>>(ipb, nullptr);
    }

    // 2) RoPE on Q, K
    rope_kernel<<<(BHt * Tt * 32) / 256, 256>>>();

    // 3) causal flash attention -> g_yhi/g_ylo
    {
        dim3 grid(Tt / 64, BHt);         // (16, 128)
        flash_attn_kernel<<<grid, 256, FL_SMEM>>>();
    }

    // 4) output projection + bias
    {
        dim3 grid(Cc / 128, Mm / 128);   // (8, 64)
        gemm_bf16x3<1><<<grid, 256, GEMM_SMEM>>>(opb, out);
    }
}

// round 4
// speedup vs baseline: 2.8394x; 1.4249x over previous
#include <cuda_runtime.h>
#include <cuda_bf16.h>
#include <math.h>
#include <stdint.h>

#define Bb 8
#define Tt 1024
#define Cc 1024
#define NHEAD 16
#define HDIM 64
#define BHt (Bb*NHEAD)     // 128
#define Mm (Bb*Tt)         // 8192
#define N1 (3*Cc)          // 3072
#define KT 32              // 1024/32 k-tiles

// ------------------------- device scratch (no allocs allowed) --------------
__device__ __nv_bfloat16 g_xhi[(size_t)Mm*Cc],  g_xlo[(size_t)Mm*Cc];
__device__ __nv_bfloat16 g_w1hi[(size_t)N1*Cc], g_w1lo[(size_t)N1*Cc];
__device__ __nv_bfloat16 g_w2hi[(size_t)Cc*Cc], g_w2lo[(size_t)Cc*Cc];
__device__ __nv_bfloat16 g_yhi[(size_t)Mm*Cc],  g_ylo[(size_t)Mm*Cc];
__device__ float g_Q [(size_t)BHt*Tt*HDIM];   // fp32 pre-rope [bh][t][d]
__device__ float g_K [(size_t)BHt*Tt*HDIM];
__device__ __nv_bfloat16 g_Qhi[(size_t)BHt*Tt*HDIM], g_Qlo[(size_t)BHt*Tt*HDIM]; // post-rope, x0.125
__device__ __nv_bfloat16 g_Khi[(size_t)BHt*Tt*HDIM], g_Klo[(size_t)BHt*Tt*HDIM];
__device__ __nv_bfloat16 g_Vthi[(size_t)BHt*HDIM*Tt], g_Vtlo[(size_t)BHt*HDIM*Tt]; // [bh][d][t]

// ------------------------------ PTX helpers --------------------------------
__device__ __forceinline__ uint32_t smem_u32(const void* p) {
    uint32_t a;
    asm("{ .reg .u64 t; cvta.to.shared.u64 t, %1; cvt.u32.u64 %0, t; }"
        : "=r"(a) : "l"(p));
    return a;
}

#define CP16(dst, src) \
    asm volatile("cp.async.cg.shared.global [%0], [%1], 16;" \
                 :: "r"(dst), "l"(src) : "memory")
#define CP_COMMIT() asm volatile("cp.async.commit_group;" ::: "memory")
#define CP_WAIT1()  asm volatile("cp.async.wait_group 1;" ::: "memory")
#define CP_WAIT0()  asm volatile("cp.async.wait_group 0;" ::: "memory")

#define LDSM4(r0, r1, r2, r3, a) \
    asm volatile("ldmatrix.sync.aligned.m8n8.x4.shared.b16 {%0,%1,%2,%3}, [%4];" \
                 : "=r"(r0), "=r"(r1), "=r"(r2), "=r"(r3) : "r"(a))

__device__ __forceinline__ void mma16816(float c[4], const uint32_t a[4],
                                         uint32_t b0, uint32_t b1) {
    asm volatile("mma.sync.aligned.m16n8k16.row.col.f32.bf16.bf16.f32 "
                 "{%0,%1,%2,%3}, {%4,%5,%6,%7}, {%8,%9}, {%0,%1,%2,%3};"
                 : "+f"(c[0]), "+f"(c[1]), "+f"(c[2]), "+f"(c[3])
                 : "r"(a[0]), "r"(a[1]), "r"(a[2]), "r"(a[3]),
                   "r"(b0), "r"(b1));
}

// two floats -> packed bf16x2 hi + residual lo
__device__ __forceinline__ void split2(float x, float y, uint32_t& hi, uint32_t& lo) {
    __nv_bfloat162 h = __floats2bfloat162_rn(x, y);
    float2 hf = __bfloat1622float2(h);
    __nv_bfloat162 l = __floats2bfloat162_rn(x - hf.x, y - hf.y);
    hi = *reinterpret_cast<uint32_t*>(&h);
    lo = *reinterpret_cast<uint32_t*>(&l);
}

// ---------------------------------------------------------------------------
// fp32 -> bf16 hi/lo split conversion
// ---------------------------------------------------------------------------
template<int W>
__global__ __launch_bounds__(256)
void cvt_kernel(const float* __restrict__ src, int n4)
{
    int i = blockIdx.x * blockDim.x + threadIdx.x;
    if (i >= n4) return;
    __nv_bfloat16* hi = (W == 0) ? g_xhi : (W == 1) ? g_w1hi : g_w2hi;
    __nv_bfloat16* lo = (W == 0) ? g_xlo : (W == 1) ? g_w1lo : g_w2lo;
    float4 v = ((const float4*)src)[i];
    __nv_bfloat162 h01 = __floats2bfloat162_rn(v.x, v.y);
    __nv_bfloat162 h23 = __floats2bfloat162_rn(v.z, v.w);
    float2 f01 = __bfloat1622float2(h01);
    float2 f23 = __bfloat1622float2(h23);
    __nv_bfloat162 l01 = __floats2bfloat162_rn(v.x - f01.x, v.y - f01.y);
    __nv_bfloat162 l23 = __floats2bfloat162_rn(v.z - f23.x, v.w - f23.y);
    ((__nv_bfloat162*)hi)[i*2]     = h01;
    ((__nv_bfloat162*)hi)[i*2 + 1] = h23;
    ((__nv_bfloat162*)lo)[i*2]     = l01;
    ((__nv_bfloat162*)lo)[i*2 + 1] = l23;
}

// ---------------------------------------------------------------------------
// bf16x3 NT GEMM via mma.sync (unchanged from R3 except V scatter -> bf16 Vt)
// ---------------------------------------------------------------------------
#define T_AHI 0
#define T_ALO 10240
#define T_BHI 20480
#define T_BLO 30720
#define STAGE_BYTES 40960
#define GEMM_SMEM (2*STAGE_BYTES)

__device__ __forceinline__ void gemm_prefetch(uint32_t sdst,
    const __nv_bfloat16* a_hi, const __nv_bfloat16* a_lo,
    const __nv_bfloat16* b_hi, const __nv_bfloat16* b_lo)
{
    CP16(sdst + T_AHI,      a_hi);
    CP16(sdst + T_AHI + 16, a_hi + 8);
    CP16(sdst + T_ALO,      a_lo);
    CP16(sdst + T_ALO + 16, a_lo + 8);
    CP16(sdst + T_BHI,      b_hi);
    CP16(sdst + T_BHI + 16, b_hi + 8);
    CP16(sdst + T_BLO,      b_lo);
    CP16(sdst + T_BLO + 16, b_lo + 8);
}

__device__ __forceinline__ void scatter_qkv(int m, int n, float2 v)
{
    int which = n >> 10, c = n & 1023;
    int h = c >> 6, d = c & 63;
    int b = m >> 10, t = m & 1023, bh = b * NHEAD + h;
    if (which == 0) {
        *(float2*)&g_Q[((size_t)bh * Tt + t) * HDIM + d] = v;
    } else if (which == 1) {
        *(float2*)&g_K[((size_t)bh * Tt + t) * HDIM + d] = v;
    } else {
        size_t i0 = ((size_t)bh * HDIM + d) * Tt + t;
        __nv_bfloat16 h0 = __float2bfloat16(v.x);
        __nv_bfloat16 h1 = __float2bfloat16(v.y);
        g_Vthi[i0]      = h0;
        g_Vtlo[i0]      = __float2bfloat16(v.x - __bfloat162float(h0));
        g_Vthi[i0 + Tt] = h1;
        g_Vtlo[i0 + Tt] = __float2bfloat16(v.y - __bfloat162float(h1));
    }
}

template<int MODE>
__global__ __launch_bounds__(256)
void gemm_bf16x3(const float* __restrict__ bias, float* __restrict__ Cout)
{
    extern __shared__ char smem[];
    const uint32_t sb = smem_u32(smem);
    const int tid  = threadIdx.x;
    const int lane = tid & 31, wid = tid >> 5;
    const int wm = wid >> 2, wn = wid & 3;
    const int m0 = blockIdx.y * 128, n0 = blockIdx.x * 128;

    const __nv_bfloat16* Ahi = (MODE == 0) ? g_xhi  : g_yhi;
    const __nv_bfloat16* Alo = (MODE == 0) ? g_xlo  : g_ylo;
    const __nv_bfloat16* Bhi = (MODE == 0) ? g_w1hi : g_w2hi;
    const __nv_bfloat16* Blo = (MODE == 0) ? g_w1lo : g_w2lo;

    const int lr = tid >> 1;
    const int lh = tid & 1;
    const size_t gA = (size_t)(m0 + lr) * Cc + lh * 16;
    const size_t gB = (size_t)(n0 + lr) * Cc + lh * 16;
    const uint32_t sOff = (uint32_t)lr * 80 + lh * 32;

    const int jq = lane >> 3, rr = lane & 7;
    const int aRow  = wm * 64 + (jq & 1) * 8 + rr;
    const int aColB = (jq >> 1) * 16;
    const int bRow  = wn * 32 + (jq >> 1) * 8 + rr;
    const int bColB = (jq & 1) * 16;

    float acc[4][4][4];
    #pragma unroll
    for (int i = 0; i < 4; i++)
        #pragma unroll
        for (int j = 0; j < 4; j++)
            #pragma unroll
            for (int e = 0; e < 4; e++) acc[i][j][e] = 0.0f;

    gemm_prefetch(sb + sOff, Ahi + gA, Alo + gA, Bhi + gB, Blo + gB);
    CP_COMMIT();

    for (int kt = 0; kt < KT; kt++) {
        const int cur = kt & 1;
        if (kt + 1 < KT) {
            const size_t ko = (size_t)(kt + 1) * 32;
            gemm_prefetch(sb + ((kt + 1) & 1) * STAGE_BYTES + sOff,
                          Ahi + gA + ko, Alo + gA + ko,
                          Bhi + gB + ko, Blo + gB + ko);
            CP_COMMIT();
            CP_WAIT1();
        } else {
            CP_WAIT0();
        }
        __syncthreads();

        const uint32_t base = sb + cur * STAGE_BYTES;
        #pragma unroll
        for (int kk = 0; kk < 2; kk++) {
            const uint32_t kB = kk * 32;
            uint32_t ah[4][4], al[4][4];
            #pragma unroll
            for (int mf = 0; mf < 4; mf++) {
                uint32_t addr = base + (uint32_t)(aRow + mf * 16) * 80 + aColB + kB;
                LDSM4(ah[mf][0], ah[mf][1], ah[mf][2], ah[mf][3], addr + T_AHI);
                LDSM4(al[mf][0], al[mf][1], al[mf][2], al[mf][3], addr + T_ALO);
            }
            uint32_t bhr[2][4], blr[2][4];
            #pragma unroll
            for (int pf = 0; pf < 2; pf++) {
                uint32_t addr = base + (uint32_t)(bRow + pf * 16) * 80 + bColB + kB;
                LDSM4(bhr[pf][0], bhr[pf][1], bhr[pf][2], bhr[pf][3], addr + T_BHI);
                LDSM4(blr[pf][0], blr[pf][1], blr[pf][2], blr[pf][3], addr + T_BLO);
            }
            #pragma unroll
            for (int mf = 0; mf < 4; mf++) {
                #pragma unroll
                for (int nt = 0; nt < 4; nt++) {
                    const int pf = nt >> 1, ix = (nt & 1) * 2;
                    mma16816(acc[mf][nt], ah[mf], bhr[pf][ix], bhr[pf][ix + 1]);
                    mma16816(acc[mf][nt], ah[mf], blr[pf][ix], blr[pf][ix + 1]);
                    mma16816(acc[mf][nt], al[mf], bhr[pf][ix], bhr[pf][ix + 1]);
                }
            }
        }
        __syncthreads();
    }

    const int gid = lane >> 2, tg = lane & 3;
    #pragma unroll
    for (int mf = 0; mf < 4; mf++) {
        #pragma unroll
        for (int nt = 0; nt < 4; nt++) {
            const int n = n0 + wn * 32 + nt * 8 + tg * 2;
            const float2 bv = *(const float2*)&bias[n];
            const int mA = m0 + wm * 64 + mf * 16 + gid;
            float2 v01 = make_float2(acc[mf][nt][0] + bv.x, acc[mf][nt][1] + bv.y);
            float2 v23 = make_float2(acc[mf][nt][2] + bv.x, acc[mf][nt][3] + bv.y);
            if (MODE == 0) {
                scatter_qkv(mA,     n, v01);
                scatter_qkv(mA + 8, n, v23);
            } else {
                *(float2*)&Cout[(size_t)mA * Cc + n]       = v01;
                *(float2*)&Cout[(size_t)(mA + 8) * Cc + n] = v23;
            }
        }
    }
}

// ---------------------------------------------------------------------------
// RoPE: read fp32 g_Q/g_K, write bf16 hi/lo (Q pre-scaled by 0.125)
// ---------------------------------------------------------------------------
__global__ __launch_bounds__(256)
void rope_kernel()
{
    int idx = blockIdx.x * blockDim.x + threadIdx.x;
    int i  = idx & 31;
    int t  = (idx >> 5) & 1023;
    int bh = idx >> 15;

    float inv = expf(-(float)i * (logf(10000.0f) / 32.0f));
    float ang = (float)t * inv;
    float sv, cv;
    sincosf(ang, &sv, &cv);

    size_t base = (size_t)(bh * Tt + t) * HDIM + 2 * i;
    float x1 = g_Q[base], x2 = g_Q[base + 1];
    float q1 = (x1 * cv - x2 * sv) * 0.125f;
    float q2 = (x2 * cv + x1 * sv) * 0.125f;
    uint32_t hi, lo;
    split2(q1, q2, hi, lo);
    *(uint32_t*)&g_Qhi[base] = hi;
    *(uint32_t*)&g_Qlo[base] = lo;

    x1 = g_K[base]; x2 = g_K[base + 1];
    float k1 = x1 * cv - x2 * sv;
    float k2 = x2 * cv + x1 * sv;
    split2(k1, k2, hi, lo);
    *(uint32_t*)&g_Khi[base] = hi;
    *(uint32_t*)&g_Klo[base] = lo;
}

// ---------------------------------------------------------------------------
// Tensor-core flash attention (bf16x3), causal. Block = (qt, bh), 128 thr.
// Warp w: q rows qt*64 + w*16 .. +15. S and PV via mma.m16n8k16.
// Smem: 6 tiles 64 x 72 bf16 (pitch 144B): Qhi Qlo Khi Klo Vhi Vlo.
// ---------------------------------------------------------------------------
#define FPITCH 144
#define SQH 0
#define SQL 9216
#define SKH 18432
#define SKL 27648
#define SVH 36864
#define SVL 46080
#define FL_SMEM 55296

__global__ __launch_bounds__(128)
void flash_attn_kernel()
{
    extern __shared__ char smem[];
    const uint32_t sb = smem_u32(smem);
    const int tid  = threadIdx.x;
    const int lane = tid & 31, w = tid >> 5;
    const int qt = blockIdx.x;     // 0..15
    const int bh = blockIdx.y;     // 0..127

    const __nv_bfloat16* Qh = g_Qhi + ((size_t)bh * Tt + qt * 64) * HDIM;
    const __nv_bfloat16* Ql = g_Qlo + ((size_t)bh * Tt + qt * 64) * HDIM;
    const __nv_bfloat16* Kh = g_Khi + (size_t)bh * Tt * HDIM;
    const __nv_bfloat16* Kl = g_Klo + (size_t)bh * Tt * HDIM;
    const __nv_bfloat16* Vh = g_Vthi + (size_t)bh * HDIM * Tt;
    const __nv_bfloat16* Vl = g_Vtlo + (size_t)bh * HDIM * Tt;

    // ---- load Q tile to smem (uint4 = 8 bf16) ----
    #pragma unroll
    for (int ii = 0; ii < 4; ii++) {
        int idx = tid + 128 * ii;            // 0..511
        int r = idx >> 3, c8 = (idx & 7) * 8;
        uint32_t so = (uint32_t)r * FPITCH + c8 * 2;
        *(uint4*)(smem + SQH + so) = *(const uint4*)&Qh[r * 64 + c8];
        *(uint4*)(smem + SQL + so) = *(const uint4*)&Ql[r * 64 + c8];
    }

    // ldmatrix geometry
    const int jq = lane >> 3, rr = lane & 7;
    const uint32_t aAddr = sb + (uint32_t)(w * 16 + (lane & 15)) * FPITCH
                         + (lane >> 4) * 16;                       // + kk*32
    const uint32_t bBase = (uint32_t)((jq >> 1) * 8 + rr) * FPITCH
                         + (jq & 1) * 16;                          // + pf*16*FPITCH + kk*32

    const int gid = lane >> 2, tg = lane & 3;
    const int rowA = w * 16 + gid;           // within q-tile
    const int rowB = rowA + 8;

    float o[8][4];
    #pragma unroll
    for (int nt = 0; nt < 8; nt++)
        #pragma unroll
        for (int e = 0; e < 4; e++) o[nt][e] = 0.0f;
    float mA = -1e30f, mB = -1e30f, lA = 0.0f, lB = 0.0f;

    for (int kt = 0; kt <= qt; kt++) {
        __syncthreads();
        // ---- load K, V tiles ----
        #pragma unroll
        for (int ii = 0; ii < 4; ii++) {
            int idx = tid + 128 * ii;
            int r = idx >> 3, c8 = (idx & 7) * 8;
            uint32_t so = (uint32_t)r * FPITCH + c8 * 2;
            *(uint4*)(smem + SKH + so) = *(const uint4*)&Kh[(kt * 64 + r) * 64 + c8];
            *(uint4*)(smem + SKL + so) = *(const uint4*)&Kl[(kt * 64 + r) * 64 + c8];
            *(uint4*)(smem + SVH + so) = *(const uint4*)&Vh[(size_t)r * Tt + kt * 64 + c8];
            *(uint4*)(smem + SVL + so) = *(const uint4*)&Vl[(size_t)r * Tt + kt * 64 + c8];
        }
        __syncthreads();

        // ---- S = Q K^T (bf16x3) ----
        float c[8][4];
        #pragma unroll
        for (int nt = 0; nt < 8; nt++)
            #pragma unroll
            for (int e = 0; e < 4; e++) c[nt][e] = 0.0f;

        #pragma unroll
        for (int kk = 0; kk < 4; kk++) {
            uint32_t aH[4], aL[4];
            LDSM4(aH[0], aH[1], aH[2], aH[3], aAddr + SQH + kk * 32);
            LDSM4(aL[0], aL[1], aL[2], aL[3], aAddr + SQL + kk * 32);
            #pragma unroll
            for (int pf = 0; pf < 4; pf++) {
                uint32_t bH[4], bL[4];
                uint32_t ba = sb + bBase + (uint32_t)pf * 16 * FPITCH + kk * 32;
                LDSM4(bH[0], bH[1], bH[2], bH[3], ba + SKH);
                LDSM4(bL[0], bL[1], bL[2], bL[3], ba + SKL);
                const int nt0 = pf * 2;
                mma16816(c[nt0],     aH, bH[0], bH[1]);
                mma16816(c[nt0],     aH, bL[0], bL[1]);
                mma16816(c[nt0],     aL, bH[0], bH[1]);
                mma16816(c[nt0 + 1], aH, bH[2], bH[3]);
                mma16816(c[nt0 + 1], aH, bL[2], bL[3]);
                mma16816(c[nt0 + 1], aL, bH[2], bH[3]);
            }
        }

        // ---- causal mask on diagonal tile ----
        if (kt == qt) {
            #pragma unroll
            for (int nt = 0; nt < 8; nt++) {
                const int colb = nt * 8 + tg * 2;
                if (colb     > rowA) c[nt][0] = -1e30f;
                if (colb + 1 > rowA) c[nt][1] = -1e30f;
                if (colb     > rowB) c[nt][2] = -1e30f;
                if (colb + 1 > rowB) c[nt][3] = -1e30f;
            }
        }

        // ---- online softmax ----
        float tmA = -1e30f, tmB = -1e30f;
        #pragma unroll
        for (int nt = 0; nt < 8; nt++) {
            tmA = fmaxf(tmA, fmaxf(c[nt][0], c[nt][1]));
            tmB = fmaxf(tmB, fmaxf(c[nt][2], c[nt][3]));
        }
        tmA = fmaxf(tmA, __shfl_xor_sync(0xffffffffu, tmA, 1));
        tmA = fmaxf(tmA, __shfl_xor_sync(0xffffffffu, tmA, 2));
        tmB = fmaxf(tmB, __shfl_xor_sync(0xffffffffu, tmB, 1));
        tmB = fmaxf(tmB, __shfl_xor_sync(0xffffffffu, tmB, 2));

        const float mnA = fmaxf(mA, tmA), mnB = fmaxf(mB, tmB);
        const float alA = __expf(mA - mnA), alB = __expf(mB - mnB);
        mA = mnA; mB = mnB;

        float sA = 0.0f, sB = 0.0f;
        #pragma unroll
        for (int nt = 0; nt < 8; nt++) {
            c[nt][0] = __expf(c[nt][0] - mnA); sA += c[nt][0];
            c[nt][1] = __expf(c[nt][1] - mnA); sA += c[nt][1];
            c[nt][2] = __expf(c[nt][2] - mnB); sB += c[nt][2];
            c[nt][3] = __expf(c[nt][3] - mnB); sB += c[nt][3];
        }
        sA += __shfl_xor_sync(0xffffffffu, sA, 1);
        sA += __shfl_xor_sync(0xffffffffu, sA, 2);
        sB += __shfl_xor_sync(0xffffffffu, sB, 1);
        sB += __shfl_xor_sync(0xffffffffu, sB, 2);
        lA = lA * alA + sA;
        lB = lB * alB + sB;
        #pragma unroll
        for (int nt = 0; nt < 8; nt++) {
            o[nt][0] *= alA; o[nt][1] *= alA;
            o[nt][2] *= alB; o[nt][3] *= alB;
        }

        // ---- PV: o += P V  (bf16x3, P fragments direct from registers) ----
        #pragma unroll
        for (int ks = 0; ks < 4; ks++) {
            uint32_t pH[4], pL[4];
            split2(c[2*ks][0],     c[2*ks][1],     pH[0], pL[0]);
            split2(c[2*ks][2],     c[2*ks][3],     pH[1], pL[1]);
            split2(c[2*ks + 1][0], c[2*ks + 1][1], pH[2], pL[2]);
            split2(c[2*ks + 1][2], c[2*ks + 1][3], pH[3], pL[3]);
            #pragma unroll
            for (int pfd = 0; pfd < 4; pfd++) {
                uint32_t bH[4], bL[4];
                uint32_t ba = sb + bBase + (uint32_t)pfd * 16 * FPITCH + ks * 32;
                LDSM4(bH[0], bH[1], bH[2], bH[3], ba + SVH);
                LDSM4(bL[0], bL[1], bL[2], bL[3], ba + SVL);
                const int nd = pfd * 2;
                mma16816(o[nd],     pH, bH[0], bH[1]);
                mma16816(o[nd],     pH, bL[0], bL[1]);
                mma16816(o[nd],     pL, bH[0], bH[1]);
                mma16816(o[nd + 1], pH, bH[2], bH[3]);
                mma16816(o[nd + 1], pH, bL[2], bL[3]);
                mma16816(o[nd + 1], pL, bH[2], bH[3]);
            }
        }
    }

    // ---- write y as bf16 hi/lo in [B,T,C] layout ----
    const int b = bh >> 4, h = bh & 15;
    const float invA = 1.0f / lA, invB = 1.0f / lB;
    const size_t ybA = ((size_t)(b * Tt + qt * 64 + rowA)) * Cc + h * HDIM;
    const size_t ybB = ((size_t)(b * Tt + qt * 64 + rowB)) * Cc + h * HDIM;
    #pragma unroll
    for (int nt = 0; nt < 8; nt++) {
        const int d = nt * 8 + tg * 2;
        uint32_t hi, lo;
        split2(o[nt][0] * invA, o[nt][1] * invA, hi, lo);
        *(uint32_t*)&g_yhi[ybA + d] = hi;
        *(uint32_t*)&g_ylo[ybA + d] = lo;
        split2(o[nt][2] * invB, o[nt][3] * invB, hi, lo);
        *(uint32_t*)&g_yhi[ybB + d] = hi;
        *(uint32_t*)&g_ylo[ybB + d] = lo;
    }
}

// ---------------------------------------------------------------------------
extern "C" void kernel_launch(void* const* d_in, const int* in_sizes, int n_in,
                              void* d_out, int out_size)
{
    (void)in_sizes; (void)n_in; (void)out_size;
    const float* x   = (const float*)d_in[0];
    const float* ipw = (const float*)d_in[1];
    const float* ipb = (const float*)d_in[2];
    const float* opw = (const float*)d_in[3];
    const float* opb = (const float*)d_in[4];
    float* out = (float*)d_out;

    cudaFuncSetAttribute(gemm_bf16x3<0>,
                         cudaFuncAttributeMaxDynamicSharedMemorySize, GEMM_SMEM);
    cudaFuncSetAttribute(gemm_bf16x3<1>,
                         cudaFuncAttributeMaxDynamicSharedMemorySize, GEMM_SMEM);
    cudaFuncSetAttribute(flash_attn_kernel,
                         cudaFuncAttributeMaxDynamicSharedMemorySize, FL_SMEM);

    // 0) hi/lo bf16 conversions of x and weights
    cvt_kernel<0><<<(Mm*Cc/4 + 255)/256, 256>>>(x,   Mm*Cc/4);
    cvt_kernel<1><<<(N1*Cc/4 + 255)/256, 256>>>(ipw, N1*Cc/4);
    cvt_kernel<2><<<(Cc*Cc/4 + 255)/256, 256>>>(opw, Cc*Cc/4);

    // 1) QKV projection + bias; Q,K fp32 head-major; V -> bf16 hi/lo transposed
    {
        dim3 grid(N1 / 128, Mm / 128);
        gemm_bf16x3<0><<<grid, 256, GEMM_SMEM>>>(ipb, nullptr);
    }

    // 2) RoPE on Q, K -> bf16 hi/lo (Q scaled by 0.125)
    rope_kernel<<<(BHt * Tt * 32) / 256, 256>>>();

    // 3) tensor-core causal flash attention -> g_yhi/g_ylo
    {
        dim3 grid(Tt / 64, BHt);
        flash_attn_kernel<<<grid, 128, FL_SMEM>>>();
    }

    // 4) output projection + bias
    {
        dim3 grid(Cc / 128, Mm / 128);
        gemm_bf16x3<1><<<grid, 256, GEMM_SMEM>>>(opb, out);
    }
}